// round 15
// baseline (speedup 1.0000x reference)
#include <cuda_runtime.h>

#define D_DIM 1024
#define L_DIM 24
#define TPB   512
#define NWARP 16
#define CPT   2           // columns per thread: 1024 / 512
#define NROW  2           // rows per group iteration
#define EPSV  1e-8f
#define FULL  0xffffffffu

// dynamic shared (floats):
//   W_enc [24*1024] | sRed[2 parity][16 warps * NROW*32 slots] | sCor[NROW*32]
// per-warp red slots, row r at +r*32: proj 0..23, ss 24, oss 25
#define SM_WE     0
#define SM_RED    (L_DIM * D_DIM)
#define SM_COR    (SM_RED + 2 * NWARP * (NROW * 32))
#define SM_FLOATS (SM_COR + NROW * 32)
#define SM_BYTES  (SM_FLOATS * 4)

__global__ __launch_bounds__(TPB, 1)
void leech_fused_kernel(const float* __restrict__ data,
                        const float* __restrict__ W_enc,
                        const float* __restrict__ b_enc,
                        const float* __restrict__ W_dec,
                        const float* __restrict__ b_dec,
                        const float* __restrict__ ecs_p,
                        const float* __restrict__ ep_p,
                        float* __restrict__ out,
                        int n_rows)
{
    extern __shared__ float smem[];
    float* sWe  = smem + SM_WE;
    float* sRed = smem + SM_RED;
    float* sCor = smem + SM_COR;

    const int t    = threadIdx.x;
    const int wid  = t >> 5;
    const int lane = t & 31;
    const int c0   = t * CPT;

    // ---- prologue: W_enc -> shared, W_dec slice -> regs (48) ----
    {
        const float4* src = reinterpret_cast<const float4*>(W_enc);
        float4* dst = reinterpret_cast<float4*>(sWe);
        #pragma unroll
        for (int i = 0; i < (L_DIM * D_DIM / 4) / TPB; ++i)
            dst[i * TPB + t] = src[i * TPB + t];
    }
    float wd[CPT][L_DIM];                // W_dec[c0+j][l] — 48 regs
    #pragma unroll
    for (int j = 0; j < CPT; ++j) {
        #pragma unroll
        for (int l = 0; l < L_DIM; l += 4) {
            float4 v = *reinterpret_cast<const float4*>(&W_dec[(c0 + j) * L_DIM + l]);
            wd[j][l + 0] = v.x; wd[j][l + 1] = v.y;
            wd[j][l + 2] = v.z; wd[j][l + 3] = v.w;
        }
    }
    const float2 bd  = *reinterpret_cast<const float2*>(&b_dec[c0]);
    const float  ecs = ecs_p[0];
    const float  ep  = ep_p[0];
    const float  benc = (lane < L_DIM) ? b_enc[lane] : 0.0f;

    // split-butterfly final lane -> value-id map (lanes with (lane&3)==3 hold dups)
    const bool dup = ((lane & 3) == 3);
    const int  vid = 12 * ((lane >> 4) & 1) + 6 * ((lane >> 3) & 1)
                   + 3 * ((lane >> 2) & 1) + ((lane & 2) ? 2 : (lane & 1));

    __syncthreads();

    const int stride  = gridDim.x;
    const int strideN = NROW * stride;
    int row0 = blockIdx.x;

    float2 d[NROW];
    #pragma unroll
    for (int r = 0; r < NROW; ++r) {
        d[r] = make_float2(0.f, 0.f);
        const int rr = row0 + r * stride;
        if (rr < n_rows)
            d[r] = *reinterpret_cast<const float2*>(&data[(size_t)rr * D_DIM + c0]);
    }

    int p = 0;   // sRed parity

    for (; row0 < n_rows; row0 += strideN) {
        float* red = sRed + p * (NWARP * (NROW * 32));

        // ---- encode NROW rows: each W_enc float2 loaded once, used NROW times ----
        float acc[NROW][L_DIM];
        #pragma unroll
        for (int l = 0; l < L_DIM; ++l) {
            const float2 w = *reinterpret_cast<const float2*>(&sWe[l * D_DIM + c0]);
            #pragma unroll
            for (int r = 0; r < NROW; ++r) {
                float a = d[r].x * w.x;
                a = fmaf(d[r].y, w.y, a);
                acc[r][l] = a;
            }
        }
        float ss[NROW];
        #pragma unroll
        for (int r = 0; r < NROW; ++r)
            ss[r] = d[r].x * d[r].x + d[r].y * d[r].y;

        // ---- prefetch next group (d[] dead after encode) ----
        float2 dn[NROW];
        #pragma unroll
        for (int r = 0; r < NROW; ++r) {
            dn[r] = make_float2(0.f, 0.f);
            const int rr = row0 + strideN + r * stride;
            if (rr < n_rows)
                dn[r] = *reinterpret_cast<const float2*>(&data[(size_t)rr * D_DIM + c0]);
        }

        // ---- NROW independent value-split butterflies ----
        float fin[NROW];
        #pragma unroll
        for (int r = 0; r < NROW; ++r) {
            float w12[12];
            #pragma unroll
            for (int i = 0; i < 12; ++i) {
                float don = (lane & 16) ? acc[r][i] : acc[r][i + 12];
                float rec = __shfl_xor_sync(FULL, don, 16);
                w12[i] = ((lane & 16) ? acc[r][i + 12] : acc[r][i]) + rec;
            }
            float w6[6];
            #pragma unroll
            for (int i = 0; i < 6; ++i) {
                float don = (lane & 8) ? w12[i] : w12[i + 6];
                float rec = __shfl_xor_sync(FULL, don, 8);
                w6[i] = ((lane & 8) ? w12[i + 6] : w12[i]) + rec;
            }
            float w3[3];
            #pragma unroll
            for (int i = 0; i < 3; ++i) {
                float don = (lane & 4) ? w6[i] : w6[i + 3];
                float rec = __shfl_xor_sync(FULL, don, 4);
                w3[i] = ((lane & 4) ? w6[i + 3] : w6[i]) + rec;
            }
            float don4 = (lane & 2) ? w3[0] : w3[2];
            float rec4 = __shfl_xor_sync(FULL, don4, 2);
            float n0 = ((lane & 2) ? w3[2] : w3[0]) + rec4;
            float n1 = w3[1] + __shfl_xor_sync(FULL, w3[1], 2);
            float don5 = (lane & 1) ? n0 : n1;
            float rec5 = __shfl_xor_sync(FULL, don5, 1);
            fin[r] = ((lane & 1) ? n1 : n0) + rec5;
        }

        #pragma unroll
        for (int off = 16; off > 0; off >>= 1) {
            #pragma unroll
            for (int r = 0; r < NROW; ++r)
                ss[r] += __shfl_xor_sync(FULL, ss[r], off);
        }

        if (!dup) {
            #pragma unroll
            for (int r = 0; r < NROW; ++r)
                red[wid * (NROW * 32) + r * 32 + vid] = fin[r];
        }
        if (lane == 3) {
            #pragma unroll
            for (int r = 0; r < NROW; ++r)
                red[wid * (NROW * 32) + r * 32 + 24] = ss[r];
        }
        __syncthreads();                               // barrier 1 (per group)

        // ---- lattice math, redundant per warp (bitwise identical) ----
        float s[NROW];
        #pragma unroll
        for (int r = 0; r < NROW; ++r) s[r] = 0.0f;
        if (lane <= L_DIM) {
            #pragma unroll
            for (int w = 0; w < NWARP; ++w) {
                #pragma unroll
                for (int r = 0; r < NROW; ++r)
                    s[r] += red[w * (NROW * 32) + r * 32 + lane];
            }
        }

        float in_e2[NROW], cor[NROW];
        #pragma unroll
        for (int r = 0; r < NROW; ++r) {
            const float in_e = sqrtf(__shfl_sync(FULL, s[r], L_DIM));
            float lp = 0.0f;
            if (lane < L_DIM)
                lp = rintf((s[r] + benc) / ecs) * ecs; // exact div + half-even round
            float q = lp * lp;
            #pragma unroll
            for (int off = 16; off > 0; off >>= 1)
                q += __shfl_xor_sync(FULL, q, off);
            const float out_e = sqrtf(q);
            const float s1  = in_e / (out_e + EPSV) * ep;
            const float lat = lp * s1;
            cor[r]   = (fabsf(lat) > ecs) ? lat : 0.0f;
            in_e2[r] = fabsf(s1) * out_e;              // ||lattice||
        }

        // ---- publish cor (all warps write IDENTICAL values: benign race) ----
        if (lane < L_DIM) {
            #pragma unroll
            for (int r = 0; r < NROW; ++r)
                sCor[r * 32 + lane] = cor[r];
        }
        __syncwarp();

        // ---- decode NROW rows: W_dec regs, cor via LDS.128 broadcast ----
        float res[NROW][CPT];
        #pragma unroll
        for (int r = 0; r < NROW; ++r) {
            res[r][0] = bd.x; res[r][1] = bd.y;
        }
        #pragma unroll
        for (int l = 0; l < L_DIM; l += 4) {
            #pragma unroll
            for (int r = 0; r < NROW; ++r) {
                const float4 c4 = *reinterpret_cast<const float4*>(&sCor[r * 32 + l]);
                const float cv[4] = {c4.x, c4.y, c4.z, c4.w};
                #pragma unroll
                for (int k = 0; k < 4; ++k) {
                    res[r][0] = fmaf(cv[k], wd[0][l + k], res[r][0]);
                    res[r][1] = fmaf(cv[k], wd[1][l + k], res[r][1]);
                }
            }
        }

        // ---- out_e2 reductions ----
        float oss[NROW];
        #pragma unroll
        for (int r = 0; r < NROW; ++r)
            oss[r] = res[r][0] * res[r][0] + res[r][1] * res[r][1];
        #pragma unroll
        for (int off = 16; off > 0; off >>= 1) {
            #pragma unroll
            for (int r = 0; r < NROW; ++r)
                oss[r] += __shfl_xor_sync(FULL, oss[r], off);
        }
        if (lane == 0) {
            #pragma unroll
            for (int r = 0; r < NROW; ++r)
                red[wid * (NROW * 32) + r * 32 + 25] = oss[r];
        }
        __syncthreads();                               // barrier 2 (per group)

        float oe2[NROW];
        #pragma unroll
        for (int r = 0; r < NROW; ++r) oe2[r] = 0.0f;
        #pragma unroll
        for (int w = 0; w < NWARP; ++w) {
            #pragma unroll
            for (int r = 0; r < NROW; ++r)
                oe2[r] += red[w * (NROW * 32) + r * 32 + 25];
        }

        #pragma unroll
        for (int r = 0; r < NROW; ++r) {
            const int rr = row0 + r * stride;
            const float s2 = in_e2[r] / (sqrtf(oe2[r]) + EPSV) * ep;
            if (rr < n_rows) {
                float2 o;
                o.x = res[r][0] * s2; o.y = res[r][1] * s2;
                *reinterpret_cast<float2*>(&out[(size_t)rr * D_DIM + c0]) = o;
            }
        }

        #pragma unroll
        for (int r = 0; r < NROW; ++r) d[r] = dn[r];
        p ^= 1;     // parity flip kills proj/oss WAR hazards across iterations
    }
}

extern "C" void kernel_launch(void* const* d_in, const int* in_sizes, int n_in,
                              void* d_out, int out_size)
{
    const float* data  = (const float*)d_in[0];
    const float* W_enc = (const float*)d_in[1];
    const float* b_enc = (const float*)d_in[2];
    const float* W_dec = (const float*)d_in[3];
    const float* b_dec = (const float*)d_in[4];
    const float* ecs   = (const float*)d_in[5];
    const float* ep    = (const float*)d_in[6];
    float* out = (float*)d_out;

    const int n_rows = in_sizes[0] / D_DIM;   // 32768

    int dev = 0;
    cudaGetDevice(&dev);
    int sms = 0;
    cudaDeviceGetAttribute(&sms, cudaDevAttrMultiProcessorCount, dev);
    if (sms <= 0) sms = 148;

    cudaFuncSetAttribute(leech_fused_kernel,
                         cudaFuncAttributeMaxDynamicSharedMemorySize, SM_BYTES);

    leech_fused_kernel<<<sms, TPB, SM_BYTES>>>(data, W_enc, b_enc, W_dec, b_dec,
                                               ecs, ep, out, n_rows);
}

// round 16
// speedup vs baseline: 1.0815x; 1.0815x over previous
#include <cuda_runtime.h>

#define D_DIM 1024
#define L_DIM 24
#define TPB   256
#define NW    8            // warps
#define CPT   4            // decode columns per thread
#define NROW  3            // rows per group
#define EPSV  1e-8f
#define FULL  0xffffffffu

// dynamic shared (floats):
//   sWe[24*1024] | sData[3*1024] | sProj[3*32] | sCor[3*32] | sOss[8*3]
// sProj row r: slots 0..23 = proj, slot 24 = ss
#define SM_WE     0
#define SM_DATA   (L_DIM * D_DIM)
#define SM_PROJ   (SM_DATA + NROW * D_DIM)
#define SM_CORR   (SM_PROJ + NROW * 32)
#define SM_OSS    (SM_CORR + NROW * 32)
#define SM_FLOATS (SM_OSS + NW * NROW)
#define SM_BYTES  (SM_FLOATS * 4)

__global__ __launch_bounds__(TPB, 1)
void leech_fused_kernel(const float* __restrict__ data,
                        const float* __restrict__ W_enc,
                        const float* __restrict__ b_enc,
                        const float* __restrict__ W_dec,
                        const float* __restrict__ b_dec,
                        const float* __restrict__ ecs_p,
                        const float* __restrict__ ep_p,
                        float* __restrict__ out,
                        int n_rows)
{
    extern __shared__ float smem[];
    float* sWe   = smem + SM_WE;
    float* sData = smem + SM_DATA;
    float* sProj = smem + SM_PROJ;
    float* sCor  = smem + SM_CORR;
    float* sOss  = smem + SM_OSS;

    const int t    = threadIdx.x;
    const int wid  = t >> 5;
    const int lane = t & 31;
    const int c0   = t * CPT;          // decode / load column base

    // ---- prologue: W_enc -> shared, W_dec slice -> regs ----
    {
        const float4* src = reinterpret_cast<const float4*>(W_enc);
        float4* dst = reinterpret_cast<float4*>(sWe);
        #pragma unroll
        for (int i = 0; i < (L_DIM * D_DIM / 4) / TPB; ++i)
            dst[i * TPB + t] = src[i * TPB + t];
    }
    float wd[CPT][L_DIM];              // W_dec[c0+j][l] — 96 regs
    #pragma unroll
    for (int j = 0; j < CPT; ++j) {
        #pragma unroll
        for (int l = 0; l < L_DIM; l += 4) {
            float4 v = *reinterpret_cast<const float4*>(&W_dec[(c0 + j) * L_DIM + l]);
            wd[j][l + 0] = v.x; wd[j][l + 1] = v.y;
            wd[j][l + 2] = v.z; wd[j][l + 3] = v.w;
        }
    }
    const float4 bd  = *reinterpret_cast<const float4*>(&b_dec[c0]);
    const float  ecs = ecs_p[0];
    const float  ep  = ep_p[0];
    const float  benc = (lane < L_DIM) ? b_enc[lane] : 0.0f;

    __syncthreads();

    const int stride  = gridDim.x;
    const int strideN = NROW * stride;
    int row0 = blockIdx.x;

    float4 d[NROW];
    #pragma unroll
    for (int r = 0; r < NROW; ++r) {
        d[r] = make_float4(0.f, 0.f, 0.f, 0.f);
        const int rr = row0 + r * stride;
        if (rr < n_rows)
            d[r] = *reinterpret_cast<const float4*>(&data[(size_t)rr * D_DIM + c0]);
    }

    for (; row0 < n_rows; row0 += strideN) {
        // ---- stage group's data tile to shared ----
        #pragma unroll
        for (int r = 0; r < NROW; ++r)
            *reinterpret_cast<float4*>(&sData[r * D_DIM + c0]) = d[r];
        __syncthreads();                           // B_data

        // ---- prefetch next group (hidden behind dots/lattice/decode) ----
        float4 dn[NROW];
        #pragma unroll
        for (int r = 0; r < NROW; ++r) {
            dn[r] = make_float4(0.f, 0.f, 0.f, 0.f);
            const int rr = row0 + strideN + r * stride;
            if (rr < n_rows)
                dn[r] = *reinterpret_cast<const float4*>(&data[(size_t)rr * D_DIM + c0]);
        }

        // ================= ENCODE: warp-direct dots =================
        // warp w owns l = w, w+8, w+16 for all NROW rows; warp<NROW also ss(row=wid)
        float acc[NROW][3];
        #pragma unroll
        for (int r = 0; r < NROW; ++r)
            acc[r][0] = acc[r][1] = acc[r][2] = 0.0f;
        float accS = 0.0f;

        const int ecol = lane * 4;
        #pragma unroll
        for (int c = 0; c < 8; ++c) {
            float4 wt[3], dat[NROW];
            #pragma unroll
            for (int j = 0; j < 3; ++j)
                wt[j] = *reinterpret_cast<const float4*>(
                            &sWe[(wid + 8 * j) * D_DIM + c * 128 + ecol]);
            #pragma unroll
            for (int r = 0; r < NROW; ++r)
                dat[r] = *reinterpret_cast<const float4*>(
                             &sData[r * D_DIM + c * 128 + ecol]);
            #pragma unroll
            for (int r = 0; r < NROW; ++r) {
                #pragma unroll
                for (int j = 0; j < 3; ++j) {
                    float a = acc[r][j];
                    a = fmaf(dat[r].x, wt[j].x, a);
                    a = fmaf(dat[r].y, wt[j].y, a);
                    a = fmaf(dat[r].z, wt[j].z, a);
                    a = fmaf(dat[r].w, wt[j].w, a);
                    acc[r][j] = a;
                }
            }
            if (wid < NROW) {
                const float4 dw = dat[wid];
                accS = fmaf(dw.x, dw.x, accS);
                accS = fmaf(dw.y, dw.y, accS);
                accS = fmaf(dw.z, dw.z, accS);
                accS = fmaf(dw.w, dw.w, accS);
            }
        }

        // ---- 9 (+1) butterfly reduces; lane0 publishes finished dots ----
        #pragma unroll
        for (int r = 0; r < NROW; ++r) {
            #pragma unroll
            for (int j = 0; j < 3; ++j) {
                float a = acc[r][j];
                #pragma unroll
                for (int off = 16; off > 0; off >>= 1)
                    a += __shfl_xor_sync(FULL, a, off);
                if (lane == 0) sProj[r * 32 + wid + 8 * j] = a;
            }
        }
        if (wid < NROW) {
            #pragma unroll
            for (int off = 16; off > 0; off >>= 1)
                accS += __shfl_xor_sync(FULL, accS, off);
            if (lane == 0) sProj[wid * 32 + 24] = accS;
        }
        __syncthreads();                           // B_proj

        // ---- lattice math: all warps redundantly (bitwise identical) ----
        float in_e2[NROW], cor[NROW];
        #pragma unroll
        for (int r = 0; r < NROW; ++r) {
            const float pr = (lane <= 24) ? sProj[r * 32 + lane] : 0.0f;
            const float in_e = sqrtf(__shfl_sync(FULL, pr, 24));
            float lp = 0.0f;
            if (lane < L_DIM)
                lp = rintf((pr + benc) / ecs) * ecs;   // exact div + half-even round
            float q = lp * lp;
            #pragma unroll
            for (int off = 16; off > 0; off >>= 1)
                q += __shfl_xor_sync(FULL, q, off);
            const float out_e = sqrtf(q);
            const float s1  = in_e / (out_e + EPSV) * ep;
            const float lat = lp * s1;
            cor[r]   = (fabsf(lat) > ecs) ? lat : 0.0f;
            in_e2[r] = fabsf(s1) * out_e;              // ||lattice||
        }

        // ---- publish cor (all warps write IDENTICAL values: benign race) ----
        if (lane < L_DIM) {
            #pragma unroll
            for (int r = 0; r < NROW; ++r)
                sCor[r * 32 + lane] = cor[r];
        }
        __syncwarp();

        // ================= DECODE (R12 shape, W_dec in regs) =================
        float res[NROW][4];
        #pragma unroll
        for (int r = 0; r < NROW; ++r) {
            res[r][0] = bd.x; res[r][1] = bd.y;
            res[r][2] = bd.z; res[r][3] = bd.w;
        }
        #pragma unroll
        for (int l = 0; l < L_DIM; l += 4) {
            #pragma unroll
            for (int r = 0; r < NROW; ++r) {
                const float4 c4 = *reinterpret_cast<const float4*>(&sCor[r * 32 + l]);
                const float cv[4] = {c4.x, c4.y, c4.z, c4.w};
                #pragma unroll
                for (int k = 0; k < 4; ++k) {
                    res[r][0] = fmaf(cv[k], wd[0][l + k], res[r][0]);
                    res[r][1] = fmaf(cv[k], wd[1][l + k], res[r][1]);
                    res[r][2] = fmaf(cv[k], wd[2][l + k], res[r][2]);
                    res[r][3] = fmaf(cv[k], wd[3][l + k], res[r][3]);
                }
            }
        }

        // ---- out_e2 partials (tree identical to R12) ----
        #pragma unroll
        for (int r = 0; r < NROW; ++r) {
            float oss = res[r][0] * res[r][0] + res[r][1] * res[r][1]
                      + res[r][2] * res[r][2] + res[r][3] * res[r][3];
            #pragma unroll
            for (int off = 16; off > 0; off >>= 1)
                oss += __shfl_xor_sync(FULL, oss, off);
            if (lane == 0) sOss[wid * NROW + r] = oss;
        }
        __syncthreads();                           // B_oss

        // ---- finalize + store ----
        #pragma unroll
        for (int r = 0; r < NROW; ++r) {
            float oe2 = 0.0f;
            #pragma unroll
            for (int w = 0; w < NW; ++w)
                oe2 += sOss[w * NROW + r];
            const float s2 = in_e2[r] / (sqrtf(oe2) + EPSV) * ep;
            const int rr = row0 + r * stride;
            if (rr < n_rows) {
                float4 o;
                o.x = res[r][0] * s2; o.y = res[r][1] * s2;
                o.z = res[r][2] * s2; o.w = res[r][3] * s2;
                *reinterpret_cast<float4*>(&out[(size_t)rr * D_DIM + c0]) = o;
            }
        }

        #pragma unroll
        for (int r = 0; r < NROW; ++r) d[r] = dn[r];
        // no parity buffers needed: B_proj/B_oss separate every read from the
        // next group's write of sData/sProj/sCor/sOss
    }
}

extern "C" void kernel_launch(void* const* d_in, const int* in_sizes, int n_in,
                              void* d_out, int out_size)
{
    const float* data  = (const float*)d_in[0];
    const float* W_enc = (const float*)d_in[1];
    const float* b_enc = (const float*)d_in[2];
    const float* W_dec = (const float*)d_in[3];
    const float* b_dec = (const float*)d_in[4];
    const float* ecs   = (const float*)d_in[5];
    const float* ep    = (const float*)d_in[6];
    float* out = (float*)d_out;

    const int n_rows = in_sizes[0] / D_DIM;   // 32768

    int dev = 0;
    cudaGetDevice(&dev);
    int sms = 0;
    cudaDeviceGetAttribute(&sms, cudaDevAttrMultiProcessorCount, dev);
    if (sms <= 0) sms = 148;

    cudaFuncSetAttribute(leech_fused_kernel,
                         cudaFuncAttributeMaxDynamicSharedMemorySize, SM_BYTES);

    leech_fused_kernel<<<sms, TPB, SM_BYTES>>>(data, W_enc, b_enc, W_dec, b_dec,
                                               ecs, ep, out, n_rows);
}

// round 17
// speedup vs baseline: 1.7272x; 1.5971x over previous
#include <cuda_runtime.h>

#define D_DIM 1024
#define L_DIM 24
#define TPB   256
#define NW    8
#define CPT   4
#define EPSV  1e-8f
#define FULL  0xffffffffu
#define MAXR  32768

// inter-kernel scratch (static __device__ globals — no allocation)
__device__ float g_cor[(size_t)MAXR * L_DIM];
__device__ float g_e2[MAXR];

// ============================ KERNEL 1: encode ============================
// R12 encode structure, NROW=2, no W_dec registers -> 2 CTAs/SM.
#define K1_NROW   2
#define K1_SMRED  (L_DIM * D_DIM)
#define K1_FLOATS (K1_SMRED + 2 * NW * (K1_NROW * 32))
#define K1_BYTES  (K1_FLOATS * 4)

__global__ __launch_bounds__(TPB, 2)
void leech_encode_kernel(const float* __restrict__ data,
                         const float* __restrict__ W_enc,
                         const float* __restrict__ b_enc,
                         const float* __restrict__ ecs_p,
                         const float* __restrict__ ep_p,
                         int n_rows)
{
    extern __shared__ float smem[];
    float* sWe  = smem;
    float* sRed = smem + K1_SMRED;

    const int t    = threadIdx.x;
    const int wid  = t >> 5;
    const int lane = t & 31;
    const int c0   = t * CPT;

    {
        const float4* src = reinterpret_cast<const float4*>(W_enc);
        float4* dst = reinterpret_cast<float4*>(sWe);
        #pragma unroll
        for (int i = 0; i < (L_DIM * D_DIM / 4) / TPB; ++i)
            dst[i * TPB + t] = src[i * TPB + t];
    }
    const float ecs = ecs_p[0];
    const float ep  = ep_p[0];
    const float benc = (lane < L_DIM) ? b_enc[lane] : 0.0f;

    const bool dup = ((lane & 3) == 3);
    const int  vid = 12 * ((lane >> 4) & 1) + 6 * ((lane >> 3) & 1)
                   + 3 * ((lane >> 2) & 1) + ((lane & 2) ? 2 : (lane & 1));

    __syncthreads();

    const int stride  = gridDim.x;
    const int strideN = K1_NROW * stride;
    int row0 = blockIdx.x;

    float4 d[K1_NROW];
    #pragma unroll
    for (int r = 0; r < K1_NROW; ++r) {
        d[r] = make_float4(0.f, 0.f, 0.f, 0.f);
        const int rr = row0 + r * stride;
        if (rr < n_rows)
            d[r] = *reinterpret_cast<const float4*>(&data[(size_t)rr * D_DIM + c0]);
    }

    int p = 0;

    for (; row0 < n_rows; row0 += strideN) {
        float* red = sRed + p * (NW * (K1_NROW * 32));

        // encode: each W_enc float4 loaded once, used K1_NROW times
        float acc[K1_NROW][L_DIM];
        #pragma unroll
        for (int l = 0; l < L_DIM; ++l) {
            float4 w = *reinterpret_cast<const float4*>(&sWe[l * D_DIM + c0]);
            #pragma unroll
            for (int r = 0; r < K1_NROW; ++r) {
                float a = d[r].x * w.x;
                a = fmaf(d[r].y, w.y, a);
                a = fmaf(d[r].z, w.z, a);
                a = fmaf(d[r].w, w.w, a);
                acc[r][l] = a;
            }
        }
        float ss[K1_NROW];
        #pragma unroll
        for (int r = 0; r < K1_NROW; ++r)
            ss[r] = d[r].x * d[r].x + d[r].y * d[r].y
                  + d[r].z * d[r].z + d[r].w * d[r].w;

        // prefetch next group
        float4 dn[K1_NROW];
        #pragma unroll
        for (int r = 0; r < K1_NROW; ++r) {
            dn[r] = make_float4(0.f, 0.f, 0.f, 0.f);
            const int rr = row0 + strideN + r * stride;
            if (rr < n_rows)
                dn[r] = *reinterpret_cast<const float4*>(&data[(size_t)rr * D_DIM + c0]);
        }

        // value-split butterflies (same tree as R12 — bitwise stable)
        float fin[K1_NROW];
        #pragma unroll
        for (int r = 0; r < K1_NROW; ++r) {
            float w12[12];
            #pragma unroll
            for (int i = 0; i < 12; ++i) {
                float don = (lane & 16) ? acc[r][i] : acc[r][i + 12];
                float rec = __shfl_xor_sync(FULL, don, 16);
                w12[i] = ((lane & 16) ? acc[r][i + 12] : acc[r][i]) + rec;
            }
            float w6[6];
            #pragma unroll
            for (int i = 0; i < 6; ++i) {
                float don = (lane & 8) ? w12[i] : w12[i + 6];
                float rec = __shfl_xor_sync(FULL, don, 8);
                w6[i] = ((lane & 8) ? w12[i + 6] : w12[i]) + rec;
            }
            float w3[3];
            #pragma unroll
            for (int i = 0; i < 3; ++i) {
                float don = (lane & 4) ? w6[i] : w6[i + 3];
                float rec = __shfl_xor_sync(FULL, don, 4);
                w3[i] = ((lane & 4) ? w6[i + 3] : w6[i]) + rec;
            }
            float don4 = (lane & 2) ? w3[0] : w3[2];
            float rec4 = __shfl_xor_sync(FULL, don4, 2);
            float n0 = ((lane & 2) ? w3[2] : w3[0]) + rec4;
            float n1 = w3[1] + __shfl_xor_sync(FULL, w3[1], 2);
            float don5 = (lane & 1) ? n0 : n1;
            float rec5 = __shfl_xor_sync(FULL, don5, 1);
            fin[r] = ((lane & 1) ? n1 : n0) + rec5;
        }
        #pragma unroll
        for (int off = 16; off > 0; off >>= 1) {
            #pragma unroll
            for (int r = 0; r < K1_NROW; ++r)
                ss[r] += __shfl_xor_sync(FULL, ss[r], off);
        }

        if (!dup) {
            #pragma unroll
            for (int r = 0; r < K1_NROW; ++r)
                red[wid * (K1_NROW * 32) + r * 32 + vid] = fin[r];
        }
        if (lane == 3) {
            #pragma unroll
            for (int r = 0; r < K1_NROW; ++r)
                red[wid * (K1_NROW * 32) + r * 32 + 24] = ss[r];
        }
        __syncthreads();     // the ONLY barrier per group (parity guards WAR)

        // lattice math: warp r handles row r (others run ahead to next encode)
        if (wid < K1_NROW) {
            const int r  = wid;
            const int rr = row0 + r * stride;
            float s = 0.0f;
            if (lane <= L_DIM) {
                #pragma unroll
                for (int w = 0; w < NW; ++w)
                    s += red[w * (K1_NROW * 32) + r * 32 + lane];
            }
            const float in_e = sqrtf(__shfl_sync(FULL, s, L_DIM));
            float lp = 0.0f;
            if (lane < L_DIM)
                lp = rintf((s + benc) / ecs) * ecs;  // exact div + half-even round
            float q = lp * lp;
            #pragma unroll
            for (int off = 16; off > 0; off >>= 1)
                q += __shfl_xor_sync(FULL, q, off);
            const float out_e = sqrtf(q);
            const float s1  = in_e / (out_e + EPSV) * ep;
            const float lat = lp * s1;
            const float cor = (fabsf(lat) > ecs) ? lat : 0.0f;
            const float in_e2 = fabsf(s1) * out_e;

            if (rr < n_rows) {
                if (lane < L_DIM) g_cor[(size_t)rr * L_DIM + lane] = cor;
                if (lane == L_DIM) g_e2[rr] = in_e2;
            }
        }

        #pragma unroll
        for (int r = 0; r < K1_NROW; ++r) d[r] = dn[r];
        p ^= 1;
    }
}

// ============================ KERNEL 2: decode ============================
// W_dec in registers, cor staged to smem with a software pipeline.
#define K2_NROW 4

__global__ __launch_bounds__(TPB, 1)
void leech_decode_kernel(const float* __restrict__ W_dec,
                         const float* __restrict__ b_dec,
                         const float* __restrict__ ep_p,
                         float* __restrict__ out,
                         int n_rows)
{
    __shared__ float sCor[2][K2_NROW * 32];
    __shared__ float sE2[2][K2_NROW];
    __shared__ float sOss[2][NW * K2_NROW];

    const int t    = threadIdx.x;
    const int wid  = t >> 5;
    const int lane = t & 31;
    const int c0   = t * CPT;

    float wd[CPT][L_DIM];                // 96 regs
    #pragma unroll
    for (int j = 0; j < CPT; ++j) {
        #pragma unroll
        for (int l = 0; l < L_DIM; l += 4) {
            float4 v = *reinterpret_cast<const float4*>(&W_dec[(c0 + j) * L_DIM + l]);
            wd[j][l + 0] = v.x; wd[j][l + 1] = v.y;
            wd[j][l + 2] = v.z; wd[j][l + 3] = v.w;
        }
    }
    const float4 bd = *reinterpret_cast<const float4*>(&b_dec[c0]);
    const float  ep = ep_p[0];

    const int stride  = gridDim.x;
    const int strideN = K2_NROW * stride;
    int row0 = blockIdx.x;

    // stage group 0 into parity 0
    if (t < K2_NROW * L_DIM) {
        const int r_ = t / L_DIM, l = t - r_ * L_DIM;
        int rr = row0 + r_ * stride;
        rr = (rr < n_rows) ? rr : (n_rows - 1);
        sCor[0][r_ * 32 + l] = g_cor[(size_t)rr * L_DIM + l];
    } else if (t < K2_NROW * L_DIM + K2_NROW) {
        const int r_ = t - K2_NROW * L_DIM;
        int rr = row0 + r_ * stride;
        rr = (rr < n_rows) ? rr : (n_rows - 1);
        sE2[0][r_] = g_e2[rr];
    }
    __syncthreads();

    int q = 0;
    for (; row0 < n_rows; row0 += strideN) {
        // ---- stage NEXT group into parity q^1 (overlaps this group's decode) ----
        if (t < K2_NROW * L_DIM) {
            const int r_ = t / L_DIM, l = t - r_ * L_DIM;
            int rr = row0 + strideN + r_ * stride;
            rr = (rr < n_rows) ? rr : (n_rows - 1);
            sCor[q ^ 1][r_ * 32 + l] = g_cor[(size_t)rr * L_DIM + l];
        } else if (t < K2_NROW * L_DIM + K2_NROW) {
            const int r_ = t - K2_NROW * L_DIM;
            int rr = row0 + strideN + r_ * stride;
            rr = (rr < n_rows) ? rr : (n_rows - 1);
            sE2[q ^ 1][r_] = g_e2[rr];
        }

        // ---- decode K2_NROW rows (tree identical to R12) ----
        float res[K2_NROW][4];
        #pragma unroll
        for (int r = 0; r < K2_NROW; ++r) {
            res[r][0] = bd.x; res[r][1] = bd.y;
            res[r][2] = bd.z; res[r][3] = bd.w;
        }
        #pragma unroll
        for (int l = 0; l < L_DIM; l += 4) {
            #pragma unroll
            for (int r = 0; r < K2_NROW; ++r) {
                const float4 c4 = *reinterpret_cast<const float4*>(&sCor[q][r * 32 + l]);
                const float cv[4] = {c4.x, c4.y, c4.z, c4.w};
                #pragma unroll
                for (int k = 0; k < 4; ++k) {
                    res[r][0] = fmaf(cv[k], wd[0][l + k], res[r][0]);
                    res[r][1] = fmaf(cv[k], wd[1][l + k], res[r][1]);
                    res[r][2] = fmaf(cv[k], wd[2][l + k], res[r][2]);
                    res[r][3] = fmaf(cv[k], wd[3][l + k], res[r][3]);
                }
            }
        }

        // ---- out_e2 partials (tree identical to R12) ----
        #pragma unroll
        for (int r = 0; r < K2_NROW; ++r) {
            float oss = res[r][0] * res[r][0] + res[r][1] * res[r][1]
                      + res[r][2] * res[r][2] + res[r][3] * res[r][3];
            #pragma unroll
            for (int off = 16; off > 0; off >>= 1)
                oss += __shfl_xor_sync(FULL, oss, off);
            if (lane == 0) sOss[q][wid * K2_NROW + r] = oss;
        }
        __syncthreads();   // publishes sOss[q] AND next group's sCor/sE2[q^1]

        // ---- finalize + store ----
        #pragma unroll
        for (int r = 0; r < K2_NROW; ++r) {
            float oe2 = 0.0f;
            #pragma unroll
            for (int w = 0; w < NW; ++w)
                oe2 += sOss[q][w * K2_NROW + r];
            const float s2 = sE2[q][r] / (sqrtf(oe2) + EPSV) * ep;
            const int rr = row0 + r * stride;
            if (rr < n_rows) {
                float4 o;
                o.x = res[r][0] * s2; o.y = res[r][1] * s2;
                o.z = res[r][2] * s2; o.w = res[r][3] * s2;
                *reinterpret_cast<float4*>(&out[(size_t)rr * D_DIM + c0]) = o;
            }
        }
        q ^= 1;
    }
}

extern "C" void kernel_launch(void* const* d_in, const int* in_sizes, int n_in,
                              void* d_out, int out_size)
{
    const float* data  = (const float*)d_in[0];
    const float* W_enc = (const float*)d_in[1];
    const float* b_enc = (const float*)d_in[2];
    const float* W_dec = (const float*)d_in[3];
    const float* b_dec = (const float*)d_in[4];
    const float* ecs   = (const float*)d_in[5];
    const float* ep    = (const float*)d_in[6];
    float* out = (float*)d_out;

    const int n_rows = in_sizes[0] / D_DIM;   // 32768

    int dev = 0;
    cudaGetDevice(&dev);
    int sms = 0;
    cudaDeviceGetAttribute(&sms, cudaDevAttrMultiProcessorCount, dev);
    if (sms <= 0) sms = 148;

    cudaFuncSetAttribute(leech_encode_kernel,
                         cudaFuncAttributeMaxDynamicSharedMemorySize, K1_BYTES);

    // kernel 1: 2 CTAs per SM (occupancy via launch_bounds(256,2))
    leech_encode_kernel<<<2 * sms, TPB, K1_BYTES>>>(data, W_enc, b_enc,
                                                    ecs, ep, n_rows);
    // kernel 2: decode (reads g_cor/g_e2 produced by kernel 1, same stream)
    leech_decode_kernel<<<sms, TPB>>>(W_dec, b_dec, ep, out, n_rows);
}